// round 13
// baseline (speedup 1.0000x reference)
#include <cuda_runtime.h>
#include <math.h>

// Problem constants: T=1024, B=64, V=256, L=256
#define CT_T 1024
#define CT_B 64
#define CT_V 256
#define CT_L 256
#define CT_S 513
#define PAD_E (-(1 << 28))

// Forward geometry (R7): 6 warps, warp covers 128 states (32 halo + 96 owned),
// 4 states/thread.
#define KS 16                 // steps per block-level exchange
#define NW 6
#define THREADS (NW * 32)     // 192
#define A_OFF 32              // Abuf index = s + A_OFF
#define A_SZ 672              // covers s in [-32, 640)

__device__ float g_per_loss[CT_B];

// Exact power-of-two scale 2^(64*d) for d <= 0 (d <= -2 -> 0).
__device__ __forceinline__ float scale64(int d) {
    d = max(d, -2);
    int bits = (127 + (d << 6)) << 23;   // d=0 -> 1.0f, d=-1 -> 2^-64
    bits = max(bits, 0);                 // d<=-2 -> 0.0f
    return __int_as_float(bits);
}

// One recursion step, 4 states/thread, shared per-thread exponent e, LAZY
// renorm: the rescale decided from the previous step's output max m is folded
// into this step's alignment scales (so the 4 renorm FMULs disappear and the
// decision leaves the dependent chain). (va, e) stays an exact representation
// at every point, so shuffled neighbor values are always consistent.
__device__ __forceinline__ void ctc_step(float va[4], int& e, float& m,
                                         const float* __restrict__ qr,
                                         int lane, int lbl1, int lbl3,
                                         float sk1f, float sk3f) {
    float q0 = qr[0];
    float q1 = qr[lbl1];
    float q3 = qr[lbl3];
    float lv = __shfl_up_sync(0xFFFFFFFFu, va[3], 1);
    int   le = __shfl_up_sync(0xFFFFFFFFu, e, 1);
    if (lane == 0) { lv = 0.0f; le = PAD_E; }

    // Pending renorm from previous step's output max (keeps max in window)
    float f; int de;
    if (m < 0x1p-32f)      { f = 0x1p64f;  de = -1; }
    else if (m >= 0x1p32f) { f = 0x1p-64f; de = 1;  }
    else                   { f = 1.0f;     de = 0;  }

    int   d  = e - le;
    float t  = scale64(-abs(d));
    float tf = t * f;
    float sof = (d < 0) ? tf : f;    // scale for own states
    float slf = (d > 0) ? tf : f;    // scale for incoming left value
    int   em  = max(e, le);

    float lvs = lv * slf;
    float v0 = va[0] * sof;
    float v1 = va[1] * sof;
    float v2 = va[2] * sof;
    float v3 = va[3] * sof;

    float n0 = (v0 + lvs) * q0;
    float n1 = fmaf(sk1f, lvs, v1 + v0) * q1;
    float n2 = (v2 + v1) * q0;
    float n3 = fmaf(sk3f, v1, v3 + v2) * q3;

    m = fmaxf(fmaxf(n0, n1), fmaxf(n2, n3));
    va[0] = n0; va[1] = n1; va[2] = n2; va[3] = n3;
    e = em + de;
}

// Fused row softmax: 8 lanes per row, each lane owns float4 indices
// seg + 8*i (i=0..7) -> contiguous 128B per 8-lane group per i (coalesced).
// xor 1,2,4 shuffles stay inside the 8-lane row group.
__device__ __forceinline__ void softmax_store(float4 x[8], float* __restrict__ dst,
                                              int seg, bool doStore) {
    float m = -1e30f;
    #pragma unroll
    for (int i = 0; i < 8; ++i)
        m = fmaxf(m, fmaxf(fmaxf(x[i].x, x[i].y), fmaxf(x[i].z, x[i].w)));
    #pragma unroll
    for (int o = 1; o < 8; o <<= 1)
        m = fmaxf(m, __shfl_xor_sync(0xFFFFFFFFu, m, o));
    float s = 0.0f;
    #pragma unroll
    for (int i = 0; i < 8; ++i) {
        x[i].x = __expf(x[i].x - m); x[i].y = __expf(x[i].y - m);
        x[i].z = __expf(x[i].z - m); x[i].w = __expf(x[i].w - m);
        s += (x[i].x + x[i].y) + (x[i].z + x[i].w);
    }
    #pragma unroll
    for (int o = 1; o < 8; o <<= 1)
        s += __shfl_xor_sync(0xFFFFFFFFu, s, o);
    float rinv = __fdividef(1.0f, s);
    if (doStore) {
        #pragma unroll
        for (int i = 0; i < 8; ++i)
            reinterpret_cast<float4*>(dst)[seg + 8 * i] =
                make_float4(x[i].x * rinv, x[i].y * rinv,
                            x[i].z * rinv, x[i].w * rinv);
    }
}

// ---------------------------------------------------------------------------
// Forward kernel: one block per batch element. R7 geometry + fused softmax +
// lazy renorm. alpha[s] = v * 2^(64e), fp32 v, shared int e per thread.
// ---------------------------------------------------------------------------
__global__ __launch_bounds__(THREADS, 1)
void ctc_forward_kernel(const int* __restrict__ labels,
                        const float* __restrict__ logits,
                        const int* __restrict__ label_length,
                        const int* __restrict__ logit_length) {
    const int b    = blockIdx.x;
    const int tid  = threadIdx.x;
    const int lane = tid & 31;
    const int warp = tid >> 5;
    const int s_base = 96 * warp - 32 + 4 * lane;   // even

    __shared__ float2 Abuf[2][A_SZ];
    __shared__ float  qblk[2][KS][CT_V];
    __shared__ float  row0q[CT_V];

    // Init both alpha buffers to dead state
    for (int i = tid; i < A_SZ; i += THREADS) {
        float2 z = make_float2(0.0f, __int_as_float(PAD_E));
        Abuf[0][i] = z;
        Abuf[1][i] = z;
    }

    const int Tb = min(max(logit_length[b], 0), CT_T);

    // Per-thread label state. r=1,3 are label positions.
    int lbl1 = 0, lbl3 = 0;
    float sk1f = 0.0f, sk3f = 0.0f;
    {
        int s1 = s_base + 1;
        if (s1 > 0 && s1 < CT_S) {
            lbl1 = labels[b * CT_L + (s1 >> 1)] & 255;
            if (s1 >= 3) {
                int pr = labels[b * CT_L + (s1 >> 1) - 1];
                sk1f = ((lbl1 != 0) && (lbl1 != pr)) ? 1.0f : 0.0f;
            }
        }
        int s3 = s_base + 3;
        if (s3 > 0 && s3 < CT_S) {
            lbl3 = labels[b * CT_L + (s3 >> 1)] & 255;
            if (s3 >= 3) {
                int pr = labels[b * CT_L + (s3 >> 1) - 1];
                sk3f = ((lbl3 != 0) && (lbl3 != pr)) ? 1.0f : 0.0f;
            }
        }
    }

    const bool qactive = (tid < 128);       // 16 rows x 8 lanes
    const int  row = tid >> 3, seg = tid & 7;

    // Initial q fill: rows t = 1..16 into qblk[0] (fused softmax)
    if (qactive) {
        int t  = 1 + row;
        int tc = max(min(t, Tb - 1), 0);
        const float4* src = reinterpret_cast<const float4*>(
                                logits + ((size_t)tc * CT_B + b) * CT_V);
        float4 x[8];
        #pragma unroll
        for (int i = 0; i < 8; ++i) x[i] = __ldg(src + seg + 8 * i);
        softmax_store(x, qblk[0][row], seg, t < Tb);
    }
    // Row 0 softmax by warp 5 (not in the q-fill set) -> row0q
    if (warp == 5) {
        const float4* src = reinterpret_cast<const float4*>(logits + (size_t)b * CT_V);
        float4 y0 = __ldg(src + 2 * lane);
        float4 y1 = __ldg(src + 2 * lane + 1);
        float m = fmaxf(fmaxf(fmaxf(y0.x, y0.y), fmaxf(y0.z, y0.w)),
                        fmaxf(fmaxf(y1.x, y1.y), fmaxf(y1.z, y1.w)));
        #pragma unroll
        for (int o = 16; o > 0; o >>= 1)
            m = fmaxf(m, __shfl_xor_sync(0xFFFFFFFFu, m, o));
        float e0 = __expf(y0.x - m), e1 = __expf(y0.y - m);
        float e2 = __expf(y0.z - m), e3 = __expf(y0.w - m);
        float e4 = __expf(y1.x - m), e5 = __expf(y1.y - m);
        float e6 = __expf(y1.z - m), e7 = __expf(y1.w - m);
        float s = ((e0 + e1) + (e2 + e3)) + ((e4 + e5) + (e6 + e7));
        #pragma unroll
        for (int o = 16; o > 0; o >>= 1)
            s += __shfl_xor_sync(0xFFFFFFFFu, s, o);
        float rinv = __fdividef(1.0f, s);
        reinterpret_cast<float4*>(row0q)[2 * lane] =
            make_float4(e0 * rinv, e1 * rinv, e2 * rinv, e3 * rinv);
        reinterpret_cast<float4*>(row0q)[2 * lane + 1] =
            make_float4(e4 * rinv, e5 * rinv, e6 * rinv, e7 * rinv);
    }
    __syncthreads();

    // alpha at t=0: s=0 (blank), s=1 (first label)
    if (tid == 0) {
        Abuf[0][A_OFF + 0] = make_float2(row0q[0], __int_as_float(0));
        Abuf[0][A_OFF + 1] = make_float2(row0q[labels[b * CT_L] & 255],
                                         __int_as_float(0));
    }
    __syncthreads();

    int p = 0;
    for (int t0 = 1; t0 < Tb; t0 += KS) {
        // Load warp's 128-state window, align exponents to one per-thread e
        float va[4]; int e; float m;
        {
            float2 f0 = Abuf[p][A_OFF + s_base + 0];
            float2 f1 = Abuf[p][A_OFF + s_base + 1];
            float2 f2 = Abuf[p][A_OFF + s_base + 2];
            float2 f3 = Abuf[p][A_OFF + s_base + 3];
            int e0 = __float_as_int(f0.y), e1 = __float_as_int(f1.y);
            int e2 = __float_as_int(f2.y), e3 = __float_as_int(f3.y);
            e = max(max(e0, e1), max(e2, e3));
            va[0] = f0.x * scale64(e0 - e);
            va[1] = f1.x * scale64(e1 - e);
            va[2] = f2.x * scale64(e2 - e);
            va[3] = f3.x * scale64(e3 - e);
            m = fmaxf(fmaxf(va[0], va[1]), fmaxf(va[2], va[3]));
        }

        // Prefetch next block's logits rows into registers
        float4 x[8];
        const bool havefetch = qactive && (t0 + KS < Tb);
        const int trow = t0 + KS + row;
        if (havefetch) {
            int tc = min(trow, Tb - 1);
            const float4* src = reinterpret_cast<const float4*>(
                                    logits + ((size_t)tc * CT_B + b) * CT_V);
            #pragma unroll
            for (int i = 0; i < 8; ++i) x[i] = __ldg(src + seg + 8 * i);
        }

        const int jmax = min(KS, Tb - t0);
        const float (*qb)[CT_V] = qblk[p];
        if (jmax == KS) {
            #pragma unroll 4
            for (int j = 0; j < KS; ++j)
                ctc_step(va, e, m, qb[j], lane, lbl1, lbl3, sk1f, sk3f);
        } else {
            for (int j = 0; j < jmax; ++j)
                ctc_step(va, e, m, qb[j], lane, lbl1, lbl3, sk1f, sk3f);
        }

        // Softmax + store prefetched rows into the other q buffer
        if (havefetch)
            softmax_store(x, qblk[p ^ 1][row], seg, trow < Tb);

        // Apply any still-pending renorm before storing, then store owned
        {
            float f = 1.0f; int de = 0;
            if (m < 0x1p-32f)      { f = 0x1p64f;  de = -1; }
            else if (m >= 0x1p32f) { f = 0x1p-64f; de = 1;  }
            float eb = __int_as_float(e + de);
            if (lane >= 8) {
                #pragma unroll
                for (int r = 0; r < 4; ++r)
                    Abuf[p ^ 1][A_OFF + s_base + r] = make_float2(va[r] * f, eb);
            }
        }
        __syncthreads();
        p ^= 1;
    }

    if (tid == 0) {
        int end = 2 * min(max(label_length[b], 0), CT_L);
        if (end > CT_S - 1) end = CT_S - 1;
        float2 fa = Abuf[p][A_OFF + end];
        float2 fb = Abuf[p][A_OFF + max(end - 1, 0)];
        int ea_ = __float_as_int(fa.y);
        int eb_ = __float_as_int(fb.y);
        int em  = max(ea_, eb_);
        double s = (double)fa.x * exp2((double)(64 * (ea_ - em)))
                 + (double)fb.x * exp2((double)(64 * (eb_ - em)));
        if (end == 0) s = 2.0 * (double)fa.x;   // logaddexp(a[0], a[0])
        s = fmax(s, 1e-300);
        double ll = log(s) + (double)em * 64.0 * 0.69314718055994530942;
        g_per_loss[b] = (float)(-ll);
    }
}

// ---------------------------------------------------------------------------
// Mean over B into d_out[0]
// ---------------------------------------------------------------------------
__global__ void mean_kernel(float* __restrict__ out) {
    __shared__ float sh[2];
    int tid = threadIdx.x;        // 64 threads
    float v = g_per_loss[tid];
    #pragma unroll
    for (int o = 16; o > 0; o >>= 1)
        v += __shfl_xor_sync(0xFFFFFFFFu, v, o);
    if ((tid & 31) == 0) sh[tid >> 5] = v;
    __syncthreads();
    if (tid == 0) out[0] = (sh[0] + sh[1]) * (1.0f / CT_B);
}

// ---------------------------------------------------------------------------
extern "C" void kernel_launch(void* const* d_in, const int* in_sizes, int n_in,
                              void* d_out, int out_size) {
    const int*   labels       = (const int*)d_in[0];   // [B, L]
    const float* logits       = (const float*)d_in[1]; // [T, B, V]
    const int*   label_length = (const int*)d_in[2];   // [B]
    const int*   logit_length = (const int*)d_in[3];   // [B]
    float*       out          = (float*)d_out;

    ctc_forward_kernel<<<CT_B, THREADS>>>(labels, logits, label_length, logit_length);
    mean_kernel<<<1, CT_B>>>(out);
}

// round 14
// speedup vs baseline: 1.0056x; 1.0056x over previous
#include <cuda_runtime.h>
#include <math.h>

// Problem constants: T=1024, B=64, V=256, L=256
#define CT_T 1024
#define CT_B 64
#define CT_V 256
#define CT_L 256
#define CT_S 513
#define PAD_E (-(1 << 28))

// Forward geometry (R7): 6 warps, warp covers 128 states (32 halo + 96 owned),
// 4 states/thread.
#define KS 16                 // steps per block-level exchange
#define NW 6
#define THREADS (NW * 32)     // 192
#define A_OFF 32              // Abuf index = s + A_OFF
#define A_SZ 672              // covers s in [-32, 640)

__device__ float g_per_loss[CT_B];

// Exact power-of-two scale 2^(64*d) for d <= 0 (d <= -2 -> 0).
__device__ __forceinline__ float scale64(int d) {
    d = max(d, -2);
    int bits = (127 + (d << 6)) << 23;   // d=0 -> 1.0f, d=-1 -> 2^-64
    bits = max(bits, 0);                 // d<=-2 -> 0.0f
    return __int_as_float(bits);
}

// One recursion step, 4 states/thread, shared per-thread exponent e, LAZY
// renorm: the rescale decided from the previous step's output max m is folded
// into this step's alignment scales (so the 4 renorm FMULs disappear and the
// decision leaves the dependent chain). (va, e) stays an exact representation
// at every point, so shuffled neighbor values are always consistent.
__device__ __forceinline__ void ctc_step(float va[4], int& e, float& m,
                                         const float* __restrict__ qr,
                                         int lane, int lbl1, int lbl3,
                                         float sk1f, float sk3f) {
    float q0 = qr[0];
    float q1 = qr[lbl1];
    float q3 = qr[lbl3];
    float lv = __shfl_up_sync(0xFFFFFFFFu, va[3], 1);
    int   le = __shfl_up_sync(0xFFFFFFFFu, e, 1);
    if (lane == 0) { lv = 0.0f; le = PAD_E; }

    // Pending renorm from previous step's output max (keeps max in window)
    float f; int de;
    if (m < 0x1p-32f)      { f = 0x1p64f;  de = -1; }
    else if (m >= 0x1p32f) { f = 0x1p-64f; de = 1;  }
    else                   { f = 1.0f;     de = 0;  }

    int   d  = e - le;
    float t  = scale64(-abs(d));
    float tf = t * f;
    float sof = (d < 0) ? tf : f;    // scale for own states
    float slf = (d > 0) ? tf : f;    // scale for incoming left value
    int   em  = max(e, le);

    float lvs = lv * slf;
    float v0 = va[0] * sof;
    float v1 = va[1] * sof;
    float v2 = va[2] * sof;
    float v3 = va[3] * sof;

    float n0 = (v0 + lvs) * q0;
    float n1 = fmaf(sk1f, lvs, v1 + v0) * q1;
    float n2 = (v2 + v1) * q0;
    float n3 = fmaf(sk3f, v1, v3 + v2) * q3;

    m = fmaxf(fmaxf(n0, n1), fmaxf(n2, n3));
    va[0] = n0; va[1] = n1; va[2] = n2; va[3] = n3;
    e = em + de;
}

// Fused row softmax: 8 lanes per row, each lane owns float4 indices
// seg + 8*i (i=0..7) -> contiguous 128B per 8-lane group per i (coalesced).
// xor 1,2,4 shuffles stay inside the 8-lane row group.
__device__ __forceinline__ void softmax_store(float4 x[8], float* __restrict__ dst,
                                              int seg, bool doStore) {
    float m = -1e30f;
    #pragma unroll
    for (int i = 0; i < 8; ++i)
        m = fmaxf(m, fmaxf(fmaxf(x[i].x, x[i].y), fmaxf(x[i].z, x[i].w)));
    #pragma unroll
    for (int o = 1; o < 8; o <<= 1)
        m = fmaxf(m, __shfl_xor_sync(0xFFFFFFFFu, m, o));
    float s = 0.0f;
    #pragma unroll
    for (int i = 0; i < 8; ++i) {
        x[i].x = __expf(x[i].x - m); x[i].y = __expf(x[i].y - m);
        x[i].z = __expf(x[i].z - m); x[i].w = __expf(x[i].w - m);
        s += (x[i].x + x[i].y) + (x[i].z + x[i].w);
    }
    #pragma unroll
    for (int o = 1; o < 8; o <<= 1)
        s += __shfl_xor_sync(0xFFFFFFFFu, s, o);
    float rinv = __fdividef(1.0f, s);
    if (doStore) {
        #pragma unroll
        for (int i = 0; i < 8; ++i)
            reinterpret_cast<float4*>(dst)[seg + 8 * i] =
                make_float4(x[i].x * rinv, x[i].y * rinv,
                            x[i].z * rinv, x[i].w * rinv);
    }
}

// ---------------------------------------------------------------------------
// Forward kernel: one block per batch element. R7 geometry + fused softmax +
// lazy renorm. alpha[s] = v * 2^(64e), fp32 v, shared int e per thread.
// ---------------------------------------------------------------------------
__global__ __launch_bounds__(THREADS, 1)
void ctc_forward_kernel(const int* __restrict__ labels,
                        const float* __restrict__ logits,
                        const int* __restrict__ label_length,
                        const int* __restrict__ logit_length) {
    const int b    = blockIdx.x;
    const int tid  = threadIdx.x;
    const int lane = tid & 31;
    const int warp = tid >> 5;
    const int s_base = 96 * warp - 32 + 4 * lane;   // even

    __shared__ float2 Abuf[2][A_SZ];
    __shared__ float  qblk[2][KS][CT_V];
    __shared__ float  row0q[CT_V];

    // Init both alpha buffers to dead state
    for (int i = tid; i < A_SZ; i += THREADS) {
        float2 z = make_float2(0.0f, __int_as_float(PAD_E));
        Abuf[0][i] = z;
        Abuf[1][i] = z;
    }

    const int Tb = min(max(logit_length[b], 0), CT_T);

    // Per-thread label state. r=1,3 are label positions.
    int lbl1 = 0, lbl3 = 0;
    float sk1f = 0.0f, sk3f = 0.0f;
    {
        int s1 = s_base + 1;
        if (s1 > 0 && s1 < CT_S) {
            lbl1 = labels[b * CT_L + (s1 >> 1)] & 255;
            if (s1 >= 3) {
                int pr = labels[b * CT_L + (s1 >> 1) - 1];
                sk1f = ((lbl1 != 0) && (lbl1 != pr)) ? 1.0f : 0.0f;
            }
        }
        int s3 = s_base + 3;
        if (s3 > 0 && s3 < CT_S) {
            lbl3 = labels[b * CT_L + (s3 >> 1)] & 255;
            if (s3 >= 3) {
                int pr = labels[b * CT_L + (s3 >> 1) - 1];
                sk3f = ((lbl3 != 0) && (lbl3 != pr)) ? 1.0f : 0.0f;
            }
        }
    }

    const bool qactive = (tid < 128);       // 16 rows x 8 lanes
    const int  row = tid >> 3, seg = tid & 7;

    // Initial q fill: rows t = 1..16 into qblk[0] (fused softmax)
    if (qactive) {
        int t  = 1 + row;
        int tc = max(min(t, Tb - 1), 0);
        const float4* src = reinterpret_cast<const float4*>(
                                logits + ((size_t)tc * CT_B + b) * CT_V);
        float4 x[8];
        #pragma unroll
        for (int i = 0; i < 8; ++i) x[i] = __ldg(src + seg + 8 * i);
        softmax_store(x, qblk[0][row], seg, t < Tb);
    }
    // Row 0 softmax by warp 5 (not in the q-fill set) -> row0q
    if (warp == 5) {
        const float4* src = reinterpret_cast<const float4*>(logits + (size_t)b * CT_V);
        float4 y0 = __ldg(src + 2 * lane);
        float4 y1 = __ldg(src + 2 * lane + 1);
        float m = fmaxf(fmaxf(fmaxf(y0.x, y0.y), fmaxf(y0.z, y0.w)),
                        fmaxf(fmaxf(y1.x, y1.y), fmaxf(y1.z, y1.w)));
        #pragma unroll
        for (int o = 16; o > 0; o >>= 1)
            m = fmaxf(m, __shfl_xor_sync(0xFFFFFFFFu, m, o));
        float e0 = __expf(y0.x - m), e1 = __expf(y0.y - m);
        float e2 = __expf(y0.z - m), e3 = __expf(y0.w - m);
        float e4 = __expf(y1.x - m), e5 = __expf(y1.y - m);
        float e6 = __expf(y1.z - m), e7 = __expf(y1.w - m);
        float s = ((e0 + e1) + (e2 + e3)) + ((e4 + e5) + (e6 + e7));
        #pragma unroll
        for (int o = 16; o > 0; o >>= 1)
            s += __shfl_xor_sync(0xFFFFFFFFu, s, o);
        float rinv = __fdividef(1.0f, s);
        reinterpret_cast<float4*>(row0q)[2 * lane] =
            make_float4(e0 * rinv, e1 * rinv, e2 * rinv, e3 * rinv);
        reinterpret_cast<float4*>(row0q)[2 * lane + 1] =
            make_float4(e4 * rinv, e5 * rinv, e6 * rinv, e7 * rinv);
    }
    __syncthreads();

    // alpha at t=0: s=0 (blank), s=1 (first label)
    if (tid == 0) {
        Abuf[0][A_OFF + 0] = make_float2(row0q[0], __int_as_float(0));
        Abuf[0][A_OFF + 1] = make_float2(row0q[labels[b * CT_L] & 255],
                                         __int_as_float(0));
    }
    __syncthreads();

    int p = 0;
    for (int t0 = 1; t0 < Tb; t0 += KS) {
        // Load warp's 128-state window, align exponents to one per-thread e
        float va[4]; int e; float m;
        {
            float2 f0 = Abuf[p][A_OFF + s_base + 0];
            float2 f1 = Abuf[p][A_OFF + s_base + 1];
            float2 f2 = Abuf[p][A_OFF + s_base + 2];
            float2 f3 = Abuf[p][A_OFF + s_base + 3];
            int e0 = __float_as_int(f0.y), e1 = __float_as_int(f1.y);
            int e2 = __float_as_int(f2.y), e3 = __float_as_int(f3.y);
            e = max(max(e0, e1), max(e2, e3));
            va[0] = f0.x * scale64(e0 - e);
            va[1] = f1.x * scale64(e1 - e);
            va[2] = f2.x * scale64(e2 - e);
            va[3] = f3.x * scale64(e3 - e);
            m = fmaxf(fmaxf(va[0], va[1]), fmaxf(va[2], va[3]));
        }

        // Prefetch next block's logits rows into registers
        float4 x[8];
        const bool havefetch = qactive && (t0 + KS < Tb);
        const int trow = t0 + KS + row;
        if (havefetch) {
            int tc = min(trow, Tb - 1);
            const float4* src = reinterpret_cast<const float4*>(
                                    logits + ((size_t)tc * CT_B + b) * CT_V);
            #pragma unroll
            for (int i = 0; i < 8; ++i) x[i] = __ldg(src + seg + 8 * i);
        }

        const int jmax = min(KS, Tb - t0);
        const float (*qb)[CT_V] = qblk[p];
        if (jmax == KS) {
            #pragma unroll 4
            for (int j = 0; j < KS; ++j)
                ctc_step(va, e, m, qb[j], lane, lbl1, lbl3, sk1f, sk3f);
        } else {
            for (int j = 0; j < jmax; ++j)
                ctc_step(va, e, m, qb[j], lane, lbl1, lbl3, sk1f, sk3f);
        }

        // Softmax + store prefetched rows into the other q buffer
        if (havefetch)
            softmax_store(x, qblk[p ^ 1][row], seg, trow < Tb);

        // Apply any still-pending renorm before storing, then store owned
        {
            float f = 1.0f; int de = 0;
            if (m < 0x1p-32f)      { f = 0x1p64f;  de = -1; }
            else if (m >= 0x1p32f) { f = 0x1p-64f; de = 1;  }
            float eb = __int_as_float(e + de);
            if (lane >= 8) {
                #pragma unroll
                for (int r = 0; r < 4; ++r)
                    Abuf[p ^ 1][A_OFF + s_base + r] = make_float2(va[r] * f, eb);
            }
        }
        __syncthreads();
        p ^= 1;
    }

    if (tid == 0) {
        int end = 2 * min(max(label_length[b], 0), CT_L);
        if (end > CT_S - 1) end = CT_S - 1;
        float2 fa = Abuf[p][A_OFF + end];
        float2 fb = Abuf[p][A_OFF + max(end - 1, 0)];
        int ea_ = __float_as_int(fa.y);
        int eb_ = __float_as_int(fb.y);
        int em  = max(ea_, eb_);
        double s = (double)fa.x * exp2((double)(64 * (ea_ - em)))
                 + (double)fb.x * exp2((double)(64 * (eb_ - em)));
        if (end == 0) s = 2.0 * (double)fa.x;   // logaddexp(a[0], a[0])
        s = fmax(s, 1e-300);
        double ll = log(s) + (double)em * 64.0 * 0.69314718055994530942;
        g_per_loss[b] = (float)(-ll);
    }
}

// ---------------------------------------------------------------------------
// Mean over B into d_out[0]
// ---------------------------------------------------------------------------
__global__ void mean_kernel(float* __restrict__ out) {
    __shared__ float sh[2];
    int tid = threadIdx.x;        // 64 threads
    float v = g_per_loss[tid];
    #pragma unroll
    for (int o = 16; o > 0; o >>= 1)
        v += __shfl_xor_sync(0xFFFFFFFFu, v, o);
    if ((tid & 31) == 0) sh[tid >> 5] = v;
    __syncthreads();
    if (tid == 0) out[0] = (sh[0] + sh[1]) * (1.0f / CT_B);
}

// ---------------------------------------------------------------------------
extern "C" void kernel_launch(void* const* d_in, const int* in_sizes, int n_in,
                              void* d_out, int out_size) {
    const int*   labels       = (const int*)d_in[0];   // [B, L]
    const float* logits       = (const float*)d_in[1]; // [T, B, V]
    const int*   label_length = (const int*)d_in[2];   // [B]
    const int*   logit_length = (const int*)d_in[3];   // [B]
    float*       out          = (float*)d_out;

    ctc_forward_kernel<<<CT_B, THREADS>>>(labels, logits, label_length, logit_length);
    mean_kernel<<<1, CT_B>>>(out);
}